// round 17
// baseline (speedup 1.0000x reference)
#include <cuda_runtime.h>
#include <cstdint>
#include <math.h>

// AFMADEBlock: incremental triangular evaluation of the MADE autoregressive
// inverse. One degree-group finalized per step (31 steps).
//
// R17 = R15 (best skeleton) + per-row compacted lane-major weight layout.
// Each W0/W1 row is consumed at exactly ONE step (known E0), so prep stores
// it pre-compacted: P block [32 lanes][e3,e3',e2,e2'] then Q block ([lane]
// [e1,e1',e0,e0'] for E0=0, [lane][e1,e1'] for E0=1). Layer-0/1 weight
// fetches become 2/2/1/1 wide LDS (vs 4/3/2/1 narrow) with identical
// crossbar bytes and less address math. Alive region is a contiguous
// prefix, so producer chunk counts (KC = 64-16*E0) are unchanged.

#define Dd 32
#define Bb 4096
#define RPW 4                  // rows per compute warp
#define NCW 7                  // compute warps per block
#define THREADS 256            // 7 compute + 1 producer warp
#define ROWS_PER_BLOCK (NCW * RPW)   // 28
#define GRID 147               // 147*28 = 4116 >= 4096

#define STEP_FLOATS 5696       // per-step staged weights (2 nets)
#define W1OFF 512
#define W2OFF 5120

// Permuted+masked weights (hidden units sorted by degree), rows compacted
// for their consumer segment's E0. ~656KB, static.
__device__ __align__(16) float g_W0p[2][32][256];
__device__ __align__(16) float g_W1p[2][256][256];
__device__ __align__(16) float g_W2p[2][256][32];
__device__ __align__(16) float g_b0p[2][256];
__device__ __align__(16) float g_b1p[2][256];
__device__ __align__(16) float g_b2[2][32];

__device__ __forceinline__ int degS(int k) {
    return (k < 72) ? (k / 9 + 1) : ((k - 72) / 8 + 9);
}
__device__ __forceinline__ int permS(int k) {
    int d, jj;
    if (k < 72) { d = k / 9 + 1;        jj = k % 9; }
    else        { d = (k - 72) / 8 + 9; jj = (k - 72) % 8; }
    return (d - 1) + 31 * jj;   // original index of k-th sorted unit
}

// Position of (e, lane, parity) within a row compacted for E0r.
__device__ __forceinline__ int lanepos(int e, int ll, int p, int E0r) {
    if (E0r == 0) return (e >= 2) ? (ll * 4 + (3 - e) * 2 + p)
                                  : (128 + ll * 4 + (1 - e) * 2 + p);
    if (E0r == 1) return (e >= 2) ? (ll * 4 + (3 - e) * 2 + p)
                                  : (128 + ll * 2 + p);        // e == 1
    if (E0r == 2) return ll * 4 + (3 - e) * 2 + p;             // e in {2,3}
    return ll * 2 + p;                                         // e == 3
}

__global__ void prep_kernel(
    const float* __restrict__ mu_W0, const float* __restrict__ mu_b0,
    const float* __restrict__ mu_W1, const float* __restrict__ mu_b1,
    const float* __restrict__ mu_W2, const float* __restrict__ mu_b2,
    const float* __restrict__ lv_W0, const float* __restrict__ lv_b0,
    const float* __restrict__ lv_W1, const float* __restrict__ lv_b1,
    const float* __restrict__ lv_W2, const float* __restrict__ lv_b2)
{
    int idx = blockIdx.x * blockDim.x + threadIdx.x;
    if (idx >= 2 * 256 * 256) return;
    int net = idx >> 16;
    int k   = (idx >> 8) & 255;   // sorted hidden row
    int c   = idx & 255;          // sorted hidden col

    const float* W0 = net ? lv_W0 : mu_W0;
    const float* b0 = net ? lv_b0 : mu_b0;
    const float* W1 = net ? lv_W1 : mu_W1;
    const float* b1 = net ? lv_b1 : mu_b1;
    const float* W2 = net ? lv_W2 : mu_W2;
    const float* b2 = net ? lv_b2 : mu_b2;

    int dk = degS(k), pk = permS(k);
    int dc = degS(c), pc = permS(c);

    int e  = c >> 6;
    int ll = (c & 63) >> 1;
    int p  = c & 1;

    // W1 row k: consumed at the step finalizing its group; E0 = off_k >> 6.
    {
        int offk = (k < 72) ? (k / 9) * 9 : 72 + ((k - 72) / 8) * 8;
        int E1r = offk >> 6;
        if (e >= E1r) {
            float v = (dc >= dk) ? W1[pk * 256 + pc] : 0.f;
            g_W1p[net][k][lanepos(e, ll, p, E1r)] = v;
        }
    }
    // W0 row k (k < 32): consumed at step t = k+1.
    if (k < 32) {
        int t = k + 1;
        int offt = (t <= 9) ? 9 * (t - 1) : 72 + 8 * (t - 9);
        int E0r = offt >> 6;                 // k == 31 -> E0r = 4: row unused
        if (e >= E0r) {
            float v = (dc >= (k + 1)) ? W0[k * 256 + pc] : 0.f;
            g_W0p[net][k][lanepos(e, ll, p, E0r)] = v;
        }
    }
    if (c < 32) g_W2p[net][k][c] = ((c + 1) > dk) ? W2[pk * 32 + c] : 0.f;
    if (k == 0) {
        g_b0p[net][c] = b0[pc];
        g_b1p[net][c] = b1[pc];
        if (c < 32) g_b2[net][c] = b2[c];
    }
}

__device__ __forceinline__ void cp16(void* s, const void* g) {
    unsigned int sa = (unsigned int)__cvta_generic_to_shared(s);
    asm volatile("cp.async.cg.shared.global [%0], [%1], 16;" :: "r"(sa), "l"(g));
}
__device__ __forceinline__ void cp_commit() {
    asm volatile("cp.async.commit_group;");
}
__device__ __forceinline__ void cp_wait_all() {
    asm volatile("cp.async.wait_group 0;");
}
// Explicit counted block barrier: legal from divergent call sites.
__device__ __forceinline__ void bar256() {
    asm volatile("bar.sync 0, 256;" ::: "memory");
}

// Packed dual-fp32 FMA: d = a*b + d (elementwise on the two f32 halves).
__device__ __forceinline__ void ffma2(float2& d, const float2& a, const float2& b) {
    asm("fma.rn.f32x2 %0, %1, %2, %0;"
        : "+l"(reinterpret_cast<unsigned long long&>(d))
        : "l"(reinterpret_cast<const unsigned long long&>(a)),
          "l"(reinterpret_cast<const unsigned long long&>(b)));
}

// Load a lane's weight pairs from a compacted row (layout per E0 above).
template<int E0>
__device__ __forceinline__ void load_wv(const float* row, int l, float2 wv[4]) {
    if (E0 == 0) {
        float4 a = *(const float4*)(row + 4 * l);
        float4 b = *(const float4*)(row + 128 + 4 * l);
        wv[3] = make_float2(a.x, a.y); wv[2] = make_float2(a.z, a.w);
        wv[1] = make_float2(b.x, b.y); wv[0] = make_float2(b.z, b.w);
    } else if (E0 == 1) {
        float4 a = *(const float4*)(row + 4 * l);
        wv[3] = make_float2(a.x, a.y); wv[2] = make_float2(a.z, a.w);
        wv[1] = *(const float2*)(row + 128 + 2 * l);
    } else if (E0 == 2) {
        float4 a = *(const float4*)(row + 4 * l);
        wv[3] = make_float2(a.x, a.y); wv[2] = make_float2(a.z, a.w);
    } else {
        wv[3] = *(const float2*)(row + 2 * l);
    }
}

// One degree-group step (both nets, RPW=4 rows).
// Lane l owns cols 64e+2l+{0,1}, e in [E0,4). CNT = group size, E0 = off>>6.
template<int CNT, int E0, bool PIPE>
__device__ __forceinline__ void do_step(
    int l, int off, const float2 y2[RPW],
    float2 a0[2][RPW][4], float2 a1[2][RPW][4], float2 aout2[2][2],
    const float* SB,
    float2 (*sH0)[9][RPW], float2 (*sH1)[9][2])
{
    // ---- layer 0: a0 += y_j * W0row ----
#pragma unroll
    for (int net = 0; net < 2; net++) {
        float2 wv0[4];
        load_wv<E0>(SB + net * 256, l, wv0);
#pragma unroll
        for (int e = E0; e < 4; e++) {
#pragma unroll
            for (int r = 0; r < RPW; r++) ffma2(a0[net][r][e], wv0[e], y2[r]);
        }
    }
    // finalize h0 group [off, off+CNT) -> sH0[net][u][r] = {h,h}
#pragma unroll
    for (int net = 0; net < 2; net++) {
#pragma unroll
        for (int e = E0; e < 4; e++) {
            int u0 = 64 * e + 2 * l - off;
            if (u0 >= 0 && u0 < CNT) {
#pragma unroll
                for (int r = 0; r < RPW; r++) {
                    float h = fmaxf(a0[net][r][e].x, 0.f);
                    sH0[net][u0][r] = make_float2(h, h);
                }
            }
            if (u0 + 1 >= 0 && u0 + 1 < CNT) {
#pragma unroll
                for (int r = 0; r < RPW; r++) {
                    float h = fmaxf(a0[net][r][e].y, 0.f);
                    sH0[net][u0 + 1][r] = make_float2(h, h);
                }
            }
        }
    }
    __syncwarp();

    // ---- layer 1: a1 += h0_group @ W1 rows ----
    if (PIPE) {
        // flatten (u, net): s = 2u + net; double-buffered loads
        float2 wv[2][4];
        float4 h01[2], h23[2];
        {
            load_wv<E0>(SB + W1OFF, l, wv[0]);   // net 0, u 0
            h01[0] = *(const float4*)&sH0[0][0][0];
            h23[0] = *(const float4*)&sH0[0][0][2];
        }
#pragma unroll
        for (int s = 0; s < 2 * CNT; s++) {
            const int cur = s & 1, nxt = cur ^ 1;
            if (s + 1 < 2 * CNT) {
                const int netn = (s + 1) & 1, un = (s + 1) >> 1;
                load_wv<E0>(SB + W1OFF + (netn * 9 + un) * 256, l, wv[nxt]);
                h01[nxt] = *(const float4*)&sH0[netn][un][0];
                h23[nxt] = *(const float4*)&sH0[netn][un][2];
            }
            const int net = s & 1;
            float2 h0 = make_float2(h01[cur].x, h01[cur].y);
            float2 h1 = make_float2(h01[cur].z, h01[cur].w);
            float2 h2 = make_float2(h23[cur].x, h23[cur].y);
            float2 h3 = make_float2(h23[cur].z, h23[cur].w);
#pragma unroll
            for (int e = E0; e < 4; e++) {
                ffma2(a1[net][0][e], wv[cur][e], h0);
                ffma2(a1[net][1][e], wv[cur][e], h1);
                ffma2(a1[net][2][e], wv[cur][e], h2);
                ffma2(a1[net][3][e], wv[cur][e], h3);
            }
        }
    } else {
#pragma unroll
        for (int u = 0; u < CNT; u++) {
#pragma unroll
            for (int net = 0; net < 2; net++) {
                float2 wv[4];
                load_wv<E0>(SB + W1OFF + (net * 9 + u) * 256, l, wv);
                float4 hq0 = *(const float4*)&sH0[net][u][0];
                float4 hq1 = *(const float4*)&sH0[net][u][2];
                float2 h0 = make_float2(hq0.x, hq0.y);
                float2 h1 = make_float2(hq0.z, hq0.w);
                float2 h2 = make_float2(hq1.x, hq1.y);
                float2 h3 = make_float2(hq1.z, hq1.w);
#pragma unroll
                for (int e = E0; e < 4; e++) {
                    ffma2(a1[net][0][e], wv[e], h0);
                    ffma2(a1[net][1][e], wv[e], h1);
                    ffma2(a1[net][2][e], wv[e], h2);
                    ffma2(a1[net][3][e], wv[e], h3);
                }
            }
        }
    }
    // finalize h1 group -> sH1[net][u][rp] = {h(2rp), h(2rp+1)}
#pragma unroll
    for (int net = 0; net < 2; net++) {
#pragma unroll
        for (int e = E0; e < 4; e++) {
            int u0 = 64 * e + 2 * l - off;
            if (u0 >= 0 && u0 < CNT) {
#pragma unroll
                for (int rp = 0; rp < 2; rp++)
                    sH1[net][u0][rp] = make_float2(
                        fmaxf(a1[net][2 * rp][e].x, 0.f),
                        fmaxf(a1[net][2 * rp + 1][e].x, 0.f));
            }
            if (u0 + 1 >= 0 && u0 + 1 < CNT) {
#pragma unroll
                for (int rp = 0; rp < 2; rp++)
                    sH1[net][u0 + 1][rp] = make_float2(
                        fmaxf(a1[net][2 * rp][e].y, 0.f),
                        fmaxf(a1[net][2 * rp + 1][e].y, 0.f));
            }
        }
    }
    __syncwarp();

    // ---- layer 2: aout += h1_group @ W2 rows (row-pair packed) ----
#pragma unroll
    for (int u = 0; u < CNT; u++) {
#pragma unroll
        for (int net = 0; net < 2; net++) {
            float wf = SB[W2OFF + (net * 9 + u) * 32 + l];
            float2 w2 = make_float2(wf, wf);
#pragma unroll
            for (int rp = 0; rp < 2; rp++) {
                float2 h2 = sH1[net][u][rp];
                ffma2(aout2[net][rp], h2, w2);
            }
        }
    }
}

// Single-warp prefetch of one step's weights (producer warp only).
// Alive data is a contiguous prefix of each row: KC = 64 - 16*E0 chunks.
template<int CNT, int E0>
__device__ __forceinline__ void prefetch_step_1w(int j, int off, int l, float* SB)
{
    constexpr int KC = 64 - 16 * E0;   // 16B chunks per W0/W1 row
#pragma unroll
    for (int net = 0; net < 2; net++) {
#pragma unroll
        for (int k = 0; k < 2; k++) {
            int q = l + 32 * k;
            if (q < KC)
                cp16(SB + net * 256 + 4 * q, &g_W0p[net][j][4 * q]);
        }
#pragma unroll
        for (int u = 0; u < CNT; u++) {
#pragma unroll
            for (int k = 0; k < 2; k++) {
                int q = l + 32 * k;
                if (q < KC)
                    cp16(SB + W1OFF + (net * 9 + u) * 256 + 4 * q,
                         &g_W1p[net][off + u][4 * q]);
            }
        }
#pragma unroll
        for (int m = 0; m < 3; m++) {
            int idx = l + 32 * m;
            if (idx < CNT * 8) {
                int u = idx >> 3, q = idx & 7;
                cp16(SB + W2OFF + (net * 9 + u) * 32 + 4 * q,
                     &g_W2p[net][off + u][4 * q]);
            }
        }
    }
}

__device__ __forceinline__ void dispatch_prefetch_1w(int t, int l, float* SB) {
    const int j = t - 1;
    const int off = (t <= 9) ? 9 * (t - 1) : 72 + 8 * (t - 9);
    if (t <= 8)       prefetch_step_1w<9, 0>(j, off, l, SB);
    else if (t <= 15) prefetch_step_1w<8, 1>(j, off, l, SB);
    else if (t <= 23) prefetch_step_1w<8, 2>(j, off, l, SB);
    else              prefetch_step_1w<8, 3>(j, off, l, SB);
}

// One segment of steps [t0, t1] with compile-time (CNT, E0) — consumer side.
// Emit computes y only for the broadcast; outputs are deferred to epilogue.
template<int CNT, int E0, bool PIPE>
__device__ __forceinline__ void run_segment(
    int t0, int t1, int l,
    const float2 xr2[2],
    float2 a0[2][RPW][4], float2 a1[2][RPW][4], float2 aout2[2][2],
    float* SW, float2 (*sH0)[9][RPW], float2 (*sH1)[9][2])
{
    for (int t = t0; t <= t1; ++t) {
        const int j = t - 1;
        // ---- broadcast y_j: y = (x - mu) * exp(-0.5*lv), lane j's value ----
        float2 y2[RPW];
#pragma unroll
        for (int rp = 0; rp < 2; rp++) {
            float nls0 = -0.5f * aout2[1][rp].x;
            float nls1 = -0.5f * aout2[1][rp].y;
            float yc0 = (xr2[rp].x - aout2[0][rp].x) * __expf(nls0);
            float yc1 = (xr2[rp].y - aout2[0][rp].y) * __expf(nls1);
            float yv0 = __shfl_sync(0xffffffffu, yc0, j);
            float yv1 = __shfl_sync(0xffffffffu, yc1, j);
            y2[2 * rp]     = make_float2(yv0, yv0);
            y2[2 * rp + 1] = make_float2(yv1, yv1);
        }

        if (t & 1) bar256();   // phase boundary: weights for t, t+1 resident

        const int off = (t <= 9) ? 9 * (t - 1) : 72 + 8 * (t - 9);
        const float* SB = SW + ((((t - 1) >> 1) & 1) * 2 + ((t - 1) & 1)) * STEP_FLOATS;
        do_step<CNT, E0, PIPE>(l, off, y2, a0, a1, aout2, SB, sH0, sH1);
    }
}

__global__ __launch_bounds__(THREADS, 1)
void afmade_kernel(const float* __restrict__ x, float* __restrict__ out)
{
    // dynamic smem: 4 step slots (2 phases x 2 steps) x STEP_FLOATS
    extern __shared__ __align__(16) unsigned char dynsm[];
    float* SW = (float*)dynsm;

    __shared__ __align__(16) float2 sH0s[NCW][2][9][RPW];  // per-warp h0 {h,h}
    __shared__ __align__(16) float2 sH1s[NCW][2][9][2];    // per-warp h1 row pairs

    const int tid = threadIdx.x;
    const int w   = tid >> 5;
    const int l   = tid & 31;

    if (w == NCW) {
        // ================= producer warp =================
        prefetch_step_1w<9, 0>(0, 0, l, SW);
        prefetch_step_1w<9, 0>(1, 9, l, SW + STEP_FLOATS);
        cp_commit();
        for (int p = 0; p < 16; ++p) {
            cp_wait_all();
            bar256();                      // phase p data visible to consumers
            if (p < 15) {
                float* NB = SW + (((p + 1) & 1) * 2) * STEP_FLOATS;
                const int t0 = 2 * p + 3;  // first step of phase p+1
                dispatch_prefetch_1w(t0, l, NB);
                if (t0 + 1 <= 31)
                    dispatch_prefetch_1w(t0 + 1, l, NB + STEP_FLOATS);
                cp_commit();
            }
        }
        return;
    }

    // ================= compute warps =================
    const int base_row_raw = blockIdx.x * ROWS_PER_BLOCK + w * RPW;
    const bool valid = (base_row_raw + RPW) <= Bb;   // warp-uniform
    const int base_row = valid ? base_row_raw : 0;

    float2 a0[2][RPW][4], a1[2][RPW][4], aout2[2][2];
    float2 xr2[2];

#pragma unroll
    for (int net = 0; net < 2; net++) {
#pragma unroll
        for (int e = 0; e < 4; e++) {
            float2 b0v = *(const float2*)&g_b0p[net][64 * e + 2 * l];
            float2 b1v = *(const float2*)&g_b1p[net][64 * e + 2 * l];
#pragma unroll
            for (int r = 0; r < RPW; r++) { a0[net][r][e] = b0v; a1[net][r][e] = b1v; }
        }
        float b2v = g_b2[net][l];
        aout2[net][0] = make_float2(b2v, b2v);
        aout2[net][1] = make_float2(b2v, b2v);
    }
#pragma unroll
    for (int rp = 0; rp < 2; rp++) {
        xr2[rp] = make_float2(x[(base_row + 2 * rp) * 32 + l],
                              x[(base_row + 2 * rp + 1) * 32 + l]);
    }

    // ---- 4 segments; PIPE in the two late segments (>=64 dead regs) ----
    run_segment<9, 0, false>( 1,  8, l, xr2, a0, a1, aout2, SW, sH0s[w], sH1s[w]);
    run_segment<8, 1, false>( 9, 15, l, xr2, a0, a1, aout2, SW, sH0s[w], sH1s[w]);
    run_segment<8, 2, true >(16, 23, l, xr2, a0, a1, aout2, SW, sH0s[w], sH1s[w]);
    run_segment<8, 3, true >(24, 31, l, xr2, a0, a1, aout2, SW, sH0s[w], sH1s[w]);

    // ---- epilogue: every col is final; emit y (coalesced) + logstd ----
    {
        float ls[RPW], yv[RPW];
#pragma unroll
        for (int rp = 0; rp < 2; rp++) {
            float nls0 = -0.5f * aout2[1][rp].x;
            float nls1 = -0.5f * aout2[1][rp].y;
            ls[2 * rp]     = -nls0;
            ls[2 * rp + 1] = -nls1;
            yv[2 * rp]     = (xr2[rp].x - aout2[0][rp].x) * __expf(nls0);
            yv[2 * rp + 1] = (xr2[rp].y - aout2[0][rp].y) * __expf(nls1);
        }
        if (valid) {
#pragma unroll
            for (int r = 0; r < RPW; r++)
                out[(base_row + r) * 32 + l] = yv[r];   // warp: 128B coalesced
        }
#pragma unroll
        for (int r = 0; r < RPW; r++) {
            float s = ls[r];
#pragma unroll
            for (int o = 16; o > 0; o >>= 1)
                s += __shfl_xor_sync(0xffffffffu, s, o);
            if (l == 0 && valid) out[Bb * Dd + base_row + r] = s;
        }
    }
}

extern "C" void kernel_launch(void* const* d_in, const int* in_sizes, int n_in,
                              void* d_out, int out_size)
{
    (void)in_sizes; (void)n_in; (void)out_size;
    const float* x = (const float*)d_in[0];

    prep_kernel<<<512, 256>>>(
        (const float*)d_in[1],  (const float*)d_in[2],  (const float*)d_in[3],
        (const float*)d_in[4],  (const float*)d_in[5],  (const float*)d_in[6],
        (const float*)d_in[7],  (const float*)d_in[8],  (const float*)d_in[9],
        (const float*)d_in[10], (const float*)d_in[11], (const float*)d_in[12]);

    const int dyn_smem = 4 * STEP_FLOATS * 4;   // 91136 B (4 step slots)
    cudaFuncSetAttribute(afmade_kernel,
                         cudaFuncAttributeMaxDynamicSharedMemorySize, dyn_smem);
    afmade_kernel<<<GRID, THREADS, dyn_smem>>>(x, (float*)d_out);
}